// round 7
// baseline (speedup 1.0000x reference)
#include <cuda_runtime.h>
#include <cuda_bf16.h>
#include <cstdint>
#include <math.h>

#define B_  8
#define L_  4096
#define D_  512
#define H_  8
#define CH  64
#define O3  1536

// ---------------- scratch (__device__ globals; no allocs allowed) ----------
__device__ float g_kv[(size_t)B_ * 1024 * L_];                 // k rows 0..511, v rows 512..1023, [b][row][L]
__device__ float g_ctxp[64 * 8 * 64 * 64];                     // [bh][split][d][e]
__device__ __nv_bfloat16 g_xhi[(size_t)B_ * L_ * D_], g_xlo[(size_t)B_ * L_ * D_];
__device__ __nv_bfloat16 g_Whi[(size_t)O3 * D_],      g_Wlo[(size_t)O3 * D_];
__device__ __nv_bfloat16 g_qhi[(size_t)B_ * L_ * D_], g_qlo[(size_t)B_ * L_ * D_];
__device__ __nv_bfloat16 g_Mhi[(size_t)B_ * D_ * D_], g_Mlo[(size_t)B_ * D_ * D_];

// ---------------- PTX helpers ---------------------------------------------
__device__ __forceinline__ uint32_t smem_u32(const void* p) {
    uint32_t a;
    asm("{ .reg .u64 t; cvta.to.shared.u64 t, %1; cvt.u32.u64 %0, t; }" : "=r"(a) : "l"(p));
    return a;
}
#define SWZ128(b) ((b) ^ (((b) >> 3) & 0x70))

__device__ __forceinline__ void cp16(uint32_t dst, const void* src) {
    asm volatile("cp.async.cg.shared.global [%0], [%1], 16;" :: "r"(dst), "l"(src));
}
#define CP_COMMIT() asm volatile("cp.async.commit_group;")

__device__ __forceinline__ void ldsm_x4(uint32_t r[4], uint32_t a) {
    asm volatile("ldmatrix.sync.aligned.m8n8.x4.shared.b16 {%0,%1,%2,%3}, [%4];"
                 : "=r"(r[0]), "=r"(r[1]), "=r"(r[2]), "=r"(r[3]) : "r"(a));
}
__device__ __forceinline__ void ldsm_x2(uint32_t r[2], uint32_t a) {
    asm volatile("ldmatrix.sync.aligned.m8n8.x2.shared.b16 {%0,%1}, [%2];"
                 : "=r"(r[0]), "=r"(r[1]) : "r"(a));
}
__device__ __forceinline__ void mma_bf16(float d[4], const uint32_t a[4], const uint32_t b[2]) {
    asm volatile("mma.sync.aligned.m16n8k16.row.col.f32.bf16.bf16.f32 "
                 "{%0,%1,%2,%3}, {%4,%5,%6,%7}, {%8,%9}, {%0,%1,%2,%3};"
                 : "+f"(d[0]), "+f"(d[1]), "+f"(d[2]), "+f"(d[3])
                 : "r"(a[0]), "r"(a[1]), "r"(a[2]), "r"(a[3]), "r"(b[0]), "r"(b[1]));
}

// ---------------- Kernel: fp32 -> bf16 hi/lo split -------------------------
__global__ __launch_bounds__(256)
void k_split(const float* __restrict__ src, int which, int n4) {
    int i = blockIdx.x * 256 + threadIdx.x;
    if (i >= n4) return;
    __nv_bfloat16* hi = which ? g_Whi : g_xhi;
    __nv_bfloat16* lo = which ? g_Wlo : g_xlo;
    float4 v = ((const float4*)src)[i];
    __nv_bfloat16 h0 = __float2bfloat16(v.x), h1 = __float2bfloat16(v.y);
    __nv_bfloat16 h2 = __float2bfloat16(v.z), h3 = __float2bfloat16(v.w);
    __nv_bfloat16 l0 = __float2bfloat16(v.x - __bfloat162float(h0));
    __nv_bfloat16 l1 = __float2bfloat16(v.y - __bfloat162float(h1));
    __nv_bfloat16 l2 = __float2bfloat16(v.z - __bfloat162float(h2));
    __nv_bfloat16 l3 = __float2bfloat16(v.w - __bfloat162float(h3));
    ((__nv_bfloat162*)hi)[i * 2 + 0] = __nv_bfloat162(h0, h1);
    ((__nv_bfloat162*)hi)[i * 2 + 1] = __nv_bfloat162(h2, h3);
    ((__nv_bfloat162*)lo)[i * 2 + 0] = __nv_bfloat162(l0, l1);
    ((__nv_bfloat162*)lo)[i * 2 + 1] = __nv_bfloat162(l2, l3);
}

// ---------------- mma.sync bf16-split GEMM ---------------------------------
// D[m,n] = sum_k A[m,k]*B[n,k], hi/lo 3-pass.  CTA 128x128, 8 warps (2m x 4n),
// K-chunk 32, 2-stage cp.async.  Smem rows: 128B = hi k0..31 | lo k0..31.
// mode 0: qkv (A=W, B=x; m0<512 -> fused q-softmax -> bf16 hi/lo, else g_kv)
// mode 1: out (A=q, B=M; D+bias -> y)
#define STAGE_B  32768
#define SMEM_MM  (2 * STAGE_B)

__global__ __launch_bounds__(256, 2)
void k_mm(float* __restrict__ Cout, const float* __restrict__ bias, int mode) {
    extern __shared__ char smem[];
    const int tid  = threadIdx.x;
    const int wid  = tid >> 5, lane = tid & 31;
    const int wm   = wid & 1;          // 0..1  (m offset wm*64)
    const int wn   = wid >> 1;         // 0..3  (n offset wn*32)
    const int b    = blockIdx.z;
    const int m0   = blockIdx.y * 128;
    const int n0   = blockIdx.x * 128;

    const uint32_t smbase = smem_u32(smem);

    const __nv_bfloat16 *Ahi, *Alo, *Bhi, *Blo;
    if (mode == 0) {
        Ahi = g_Whi + (size_t)m0 * D_;              Alo = g_Wlo + (size_t)m0 * D_;
        Bhi = g_xhi + ((size_t)b * L_ + n0) * D_;   Blo = g_xlo + ((size_t)b * L_ + n0) * D_;
    } else {
        Ahi = g_qhi + ((size_t)b * L_ + m0) * D_;   Alo = g_qlo + ((size_t)b * L_ + m0) * D_;
        Bhi = g_Mhi + ((size_t)b * D_ + n0) * D_;   Blo = g_Mlo + ((size_t)b * D_ + n0) * D_;
    }

    // stage loader: 2048 cp16 / 256 threads = 8 each
    auto load_stage = [&](int s, int d0) {
        uint32_t base = smbase + s * STAGE_B;
#pragma unroll
        for (int i = 0; i < 8; i++) {
            int id = i * 256 + tid;                // 0..2047
            int reg = id >> 10;                    // 0 = A, 1 = B
            int r   = (id >> 3) & 127;
            int u   = id & 7;                      // 0..3 hi, 4..7 lo
            const __nv_bfloat16* hp = reg ? Bhi : Ahi;
            const __nv_bfloat16* lp = reg ? Blo : Alo;
            const __nv_bfloat16* src = (u < 4)
                ? hp + (size_t)r * D_ + d0 + u * 8
                : lp + (size_t)r * D_ + d0 + (u - 4) * 8;
            cp16(base + reg * 16384 + SWZ128((uint32_t)(r * 128 + u * 16)), src);
        }
        CP_COMMIT();
    };

    float acc[4][4][4];
#pragma unroll
    for (int i = 0; i < 4; i++)
#pragma unroll
        for (int j = 0; j < 4; j++)
#pragma unroll
            for (int k = 0; k < 4; k++) acc[i][j][k] = 0.f;

    // precomputed lane address components
    const uint32_t a_row = wm * 64 + (lane & 15);
    const uint32_t a_ub  = (lane >> 4);            // 0..1
    const uint32_t b_row = wn * 32 + (lane & 7);
    const uint32_t b_ub  = (lane >> 3) & 1;

    load_stage(0, 0);

    for (int kc = 0; kc < 16; kc++) {
        int s = kc & 1;
        if (kc + 1 < 16) {
            load_stage(s ^ 1, (kc + 1) * 32);
            asm volatile("cp.async.wait_group 1;");
        } else {
            asm volatile("cp.async.wait_group 0;");
        }
        __syncthreads();

        uint32_t smA = smbase + s * STAGE_B;
        uint32_t smB = smA + 16384;
#pragma unroll
        for (int sl = 0; sl < 2; sl++) {           // k16 slices within chunk
            uint32_t ah[4][4], al[4][4];
#pragma unroll
            for (int mt = 0; mt < 4; mt++) {
                uint32_t row = a_row + mt * 16;
                ldsm_x4(ah[mt], smA + SWZ128(row * 128 + (sl * 2 + a_ub) * 16));
                ldsm_x4(al[mt], smA + SWZ128(row * 128 + (4 + sl * 2 + a_ub) * 16));
            }
#pragma unroll
            for (int nt = 0; nt < 4; nt++) {
                uint32_t row = b_row + nt * 8;
                uint32_t bh[2], bl[2];
                ldsm_x2(bh, smB + SWZ128(row * 128 + (sl * 2 + b_ub) * 16));
                ldsm_x2(bl, smB + SWZ128(row * 128 + (4 + sl * 2 + b_ub) * 16));
#pragma unroll
                for (int mt = 0; mt < 4; mt++) {
                    mma_bf16(acc[mt][nt], ah[mt], bh);
                    mma_bf16(acc[mt][nt], ah[mt], bl);
                    mma_bf16(acc[mt][nt], al[mt], bh);
                }
            }
        }
        __syncthreads();
    }

    // ---- epilogue via smem, two 64-col halves ----
    float* ep = (float*)smem;                      // [128][65]
    float* inv_s = ep + 128 * 65;                  // [2][64]
    for (int p = 0; p < 2; p++) {
        if ((wn >> 1) == p) {
            int cb = (wn & 1) * 32;
#pragma unroll
            for (int mt = 0; mt < 4; mt++)
#pragma unroll
                for (int nt = 0; nt < 4; nt++) {
                    int row = wm * 64 + mt * 16 + (lane >> 2);
                    int col = cb + nt * 8 + (lane & 3) * 2;
                    ep[row * 65 + col]           = acc[mt][nt][0];
                    ep[row * 65 + col + 1]       = acc[mt][nt][1];
                    ep[(row + 8) * 65 + col]     = acc[mt][nt][2];
                    ep[(row + 8) * 65 + col + 1] = acc[mt][nt][3];
                }
        }
        __syncthreads();
        int c0 = p * 64;
        if (mode == 0 && m0 < 512) {
            // fused q-softmax over channel dim (64 rows per head, 2 heads/tile)
            if (tid < 128) {
                int c  = tid & 63;
                int r0 = (tid >> 6) * 64;
                float mx = -3.0e38f;
#pragma unroll 8
                for (int r = 0; r < 64; r++) mx = fmaxf(mx, ep[(r0 + r) * 65 + c]);
                float s = 0.f;
#pragma unroll 8
                for (int r = 0; r < 64; r++) {
                    float e = expf(ep[(r0 + r) * 65 + c] - mx);
                    ep[(r0 + r) * 65 + c] = e;
                    s += e;
                }
                inv_s[tid] = 1.0f / s;
            }
            __syncthreads();
            // write bf16 hi/lo transposed: g_q* [b][l][channel]
#pragma unroll
            for (int i = 0; i < 8; i++) {
                int id = tid + 256 * i;
                int c = id >> 5, mg = id & 31;
                float inv = inv_s[(mg >> 4) * 64 + c];
                float x0 = ep[(mg * 4 + 0) * 65 + c] * inv;
                float x1 = ep[(mg * 4 + 1) * 65 + c] * inv;
                float x2 = ep[(mg * 4 + 2) * 65 + c] * inv;
                float x3 = ep[(mg * 4 + 3) * 65 + c] * inv;
                __nv_bfloat16 h0 = __float2bfloat16(x0), h1 = __float2bfloat16(x1);
                __nv_bfloat16 h2 = __float2bfloat16(x2), h3 = __float2bfloat16(x3);
                __nv_bfloat16 q0 = __float2bfloat16(x0 - __bfloat162float(h0));
                __nv_bfloat16 q1 = __float2bfloat16(x1 - __bfloat162float(h1));
                __nv_bfloat16 q2 = __float2bfloat16(x2 - __bfloat162float(h2));
                __nv_bfloat16 q3 = __float2bfloat16(x3 - __bfloat162float(h3));
                size_t idx = ((size_t)b * L_ + n0 + c0 + c) * D_ + m0 + mg * 4;
                union { __nv_bfloat162 v[2]; uint2 u; } ph, pl;
                ph.v[0] = __nv_bfloat162(h0, h1); ph.v[1] = __nv_bfloat162(h2, h3);
                pl.v[0] = __nv_bfloat162(q0, q1); pl.v[1] = __nv_bfloat162(q2, q3);
                *(uint2*)(g_qhi + idx) = ph.u;
                *(uint2*)(g_qlo + idx) = pl.u;
            }
        } else {
            float* dst; int ldc;
            if (mode == 0) { dst = g_kv + ((size_t)b * 1024 + (m0 - 512)) * L_; ldc = L_; }
            else           { dst = Cout + ((size_t)b * L_ + m0) * D_;           ldc = D_; }
#pragma unroll
            for (int i = 0; i < 8; i++) {
                int id = tid + 256 * i;
                int m = id >> 4, g = id & 15;
                float4 v;
                v.x = ep[m * 65 + g * 4 + 0];
                v.y = ep[m * 65 + g * 4 + 1];
                v.z = ep[m * 65 + g * 4 + 2];
                v.w = ep[m * 65 + g * 4 + 3];
                if (mode == 1) {
                    v.x += __ldg(bias + n0 + c0 + g * 4 + 0);
                    v.y += __ldg(bias + n0 + c0 + g * 4 + 1);
                    v.z += __ldg(bias + n0 + c0 + g * 4 + 2);
                    v.w += __ldg(bias + n0 + c0 + g * 4 + 3);
                }
                *(float4*)(dst + (size_t)m * ldc + n0 + c0 + g * 4) = v;
            }
        }
        __syncthreads();
    }
}

// ---------------- softmax over L for k rows (register-cached) --------------
__global__ __launch_bounds__(256)
void k_softmax_rows() {
    const int r = blockIdx.x, b = blockIdx.y;
    float* row = g_kv + ((size_t)b * 1024 + r) * L_;
    const int tid = threadIdx.x;
    __shared__ float red[8], bc[2];

    float4 v[4];
    float mx = -3.0e38f;
#pragma unroll
    for (int j = 0; j < 4; j++) {
        v[j] = ((const float4*)row)[tid + 256 * j];
        mx = fmaxf(mx, fmaxf(fmaxf(v[j].x, v[j].y), fmaxf(v[j].z, v[j].w)));
    }
#pragma unroll
    for (int o = 16; o; o >>= 1) mx = fmaxf(mx, __shfl_xor_sync(0xffffffffu, mx, o));
    if ((tid & 31) == 0) red[tid >> 5] = mx;
    __syncthreads();
    if (tid < 32) {
        float m2 = (tid < 8) ? red[tid] : -3.0e38f;
#pragma unroll
        for (int o = 4; o; o >>= 1) m2 = fmaxf(m2, __shfl_xor_sync(0xffffffffu, m2, o));
        if (tid == 0) bc[0] = m2;
    }
    __syncthreads();
    const float m = bc[0];

    float s = 0.f;
#pragma unroll
    for (int j = 0; j < 4; j++) {
        v[j].x = expf(v[j].x - m); v[j].y = expf(v[j].y - m);
        v[j].z = expf(v[j].z - m); v[j].w = expf(v[j].w - m);
        s += (v[j].x + v[j].y) + (v[j].z + v[j].w);
    }
#pragma unroll
    for (int o = 16; o; o >>= 1) s += __shfl_xor_sync(0xffffffffu, s, o);
    if ((tid & 31) == 0) red[tid >> 5] = s;
    __syncthreads();
    if (tid < 32) {
        float s2 = (tid < 8) ? red[tid] : 0.f;
#pragma unroll
        for (int o = 4; o; o >>= 1) s2 += __shfl_xor_sync(0xffffffffu, s2, o);
        if (tid == 0) bc[1] = s2;
    }
    __syncthreads();
    const float inv = 1.0f / bc[1];
#pragma unroll
    for (int j = 0; j < 4; j++) {
        v[j].x *= inv; v[j].y *= inv; v[j].z *= inv; v[j].w *= inv;
        ((float4*)row)[tid + 256 * j] = v[j];
    }
}

// ---------------- context partials: ctx[d,e] = sum_n k[d,n] v[e,n] ---------
// grid (64 bh, 8 splits of 512), 256 threads (16x16), 4x4 per thread.
__global__ __launch_bounds__(256)
void k_ctx() {
    const int bh = blockIdx.x, sp = blockIdx.y;
    const int b = bh >> 3, h = bh & 7;
    const float* kbase = g_kv + ((size_t)b * 1024 + h * CH) * L_;
    const float* vbase = g_kv + ((size_t)b * 1024 + 512 + h * CH) * L_;

    __shared__ float ks[64][65];
    __shared__ float vs[64][65];
    const int tid = threadIdx.x;
    const int tx = tid & 15, ty = tid >> 4;

    float acc[4][4];
#pragma unroll
    for (int i = 0; i < 4; i++)
#pragma unroll
        for (int j = 0; j < 4; j++) acc[i][j] = 0.f;

    for (int chn = 0; chn < 8; chn++) {
        int n0 = sp * 512 + chn * 64;
#pragma unroll
        for (int i = 0; i < 4; i++) {
            int id = tid + 256 * i;
            int row = id >> 4, col = (id & 15) * 4;
            float4 kv = *(const float4*)(kbase + (size_t)row * L_ + n0 + col);
            ks[row][col+0]=kv.x; ks[row][col+1]=kv.y; ks[row][col+2]=kv.z; ks[row][col+3]=kv.w;
            float4 vv = *(const float4*)(vbase + (size_t)row * L_ + n0 + col);
            vs[row][col+0]=vv.x; vs[row][col+1]=vv.y; vs[row][col+2]=vv.z; vs[row][col+3]=vv.w;
        }
        __syncthreads();
#pragma unroll 4
        for (int nn = 0; nn < 64; nn++) {
            float kr[4], vr[4];
#pragma unroll
            for (int i = 0; i < 4; i++) kr[i] = ks[ty * 4 + i][nn];
#pragma unroll
            for (int j = 0; j < 4; j++) vr[j] = vs[tx + 16 * j][nn];
#pragma unroll
            for (int i = 0; i < 4; i++)
#pragma unroll
                for (int j = 0; j < 4; j++) acc[i][j] = fmaf(kr[i], vr[j], acc[i][j]);
        }
        __syncthreads();
    }
    float* out = g_ctxp + (size_t)(bh * 8 + sp) * 4096;
#pragma unroll
    for (int i = 0; i < 4; i++)
#pragma unroll
        for (int j = 0; j < 4; j++)
            out[(size_t)(ty * 4 + i) * 64 + tx + 16 * j] = acc[i][j];
}

// ---------------- reduce ctx + M = Wout-contract, emit bf16 hi/lo ----------
__global__ __launch_bounds__(256)
void k_M(const float* __restrict__ Wout) {
    const int bh = blockIdx.x;
    const int b = bh >> 3, h = bh & 7;
    __shared__ float ctxs[64][65];
    const int tid = threadIdx.x;

    for (int e0 = tid; e0 < 4096; e0 += 256) {
        float sum = 0.f;
        const float* p = g_ctxp + (size_t)bh * 8 * 4096 + e0;
#pragma unroll
        for (int s = 0; s < 8; s++) sum += p[(size_t)s * 4096];
        ctxs[e0 >> 6][e0 & 63] = sum;
    }
    __syncthreads();

    const int d = tid & 63, dq = tid >> 6;
    for (int dout = dq; dout < D_; dout += 4) {
        const float* wrow = Wout + (size_t)dout * D_ + h * CH;
        float sum = 0.f;
#pragma unroll
        for (int e = 0; e < CH; e++) sum = fmaf(__ldg(wrow + e), ctxs[d][e], sum);
        size_t o = (size_t)b * D_ * D_ + (size_t)dout * D_ + h * CH + d;
        __nv_bfloat16 hi = __float2bfloat16(sum);
        g_Mhi[o] = hi;
        g_Mlo[o] = __float2bfloat16(sum - __bfloat162float(hi));
    }
}

// ---------------------------------------------------------------------------
extern "C" void kernel_launch(void* const* d_in, const int* in_sizes, int n_in,
                              void* d_out, int out_size) {
    const float* x    = (const float*)d_in[0];
    const float* Wqkv = (const float*)d_in[1];
    const float* Wout = (const float*)d_in[2];
    const float* bout = (const float*)d_in[3];
    float* y = (float*)d_out;

    cudaFuncSetAttribute(k_mm, cudaFuncAttributeMaxDynamicSharedMemorySize, SMEM_MM);

    int n4x = B_ * L_ * D_ / 4;
    int n4w = O3 * D_ / 4;
    k_split<<<(n4x + 255) / 256, 256>>>(x, 0, n4x);
    k_split<<<(n4w + 255) / 256, 256>>>(Wqkv, 1, n4w);

    k_mm<<<dim3(32, 12, B_), 256, SMEM_MM>>>(nullptr, nullptr, 0);    // qkv
    k_softmax_rows<<<dim3(512, B_), 256>>>();
    k_ctx<<<dim3(64, 8), 256>>>();
    k_M<<<64, 256>>>(Wout);
    k_mm<<<dim3(4, 32, B_), 256, SMEM_MM>>>(y, bout, 1);              // out
}

// round 9
// speedup vs baseline: 2.0554x; 2.0554x over previous
#include <cuda_runtime.h>
#include <cuda_fp16.h>
#include <cstdint>
#include <math.h>

#define B_  8
#define L_  4096
#define D_  512
#define H_  8
#define CH  64
#define O3  1536

// ---------------- scratch (__device__ globals; no allocs allowed) ----------
__device__ float g_kv[(size_t)B_ * 1024 * L_];                 // k rows 0..511, v rows 512..1023, [b][row][L]
__device__ float g_ctxp[64 * 8 * 64 * 64];                     // [bh][split][d][e]
__device__ __half g_Wh[(size_t)O3 * D_];                       // W fp16 (A operand, hi only)
__device__ __half g_xh[(size_t)B_ * L_ * D_], g_xl[(size_t)B_ * L_ * D_];
__device__ __half g_qh[(size_t)B_ * L_ * D_];                  // q fp16 [b][l][c]
__device__ __half g_Mh[(size_t)B_ * D_ * D_], g_Ml[(size_t)B_ * D_ * D_];

// ---------------- PTX helpers ---------------------------------------------
__device__ __forceinline__ uint32_t smem_u32(const void* p) {
    uint32_t a;
    asm("{ .reg .u64 t; cvta.to.shared.u64 t, %1; cvt.u32.u64 %0, t; }" : "=r"(a) : "l"(p));
    return a;
}
#define SWZ128(b) ((b) ^ (((b) >> 3) & 0x70))

__device__ __forceinline__ void cp16(uint32_t dst, const void* src) {
    asm volatile("cp.async.cg.shared.global [%0], [%1], 16;" :: "r"(dst), "l"(src));
}
#define CP_COMMIT() asm volatile("cp.async.commit_group;")

__device__ __forceinline__ void ldsm_x4(uint32_t r[4], uint32_t a) {
    asm volatile("ldmatrix.sync.aligned.m8n8.x4.shared.b16 {%0,%1,%2,%3}, [%4];"
                 : "=r"(r[0]), "=r"(r[1]), "=r"(r[2]), "=r"(r[3]) : "r"(a));
}
__device__ __forceinline__ void ldsm_x2(uint32_t r[2], uint32_t a) {
    asm volatile("ldmatrix.sync.aligned.m8n8.x2.shared.b16 {%0,%1}, [%2];"
                 : "=r"(r[0]), "=r"(r[1]) : "r"(a));
}
__device__ __forceinline__ void mma_f16(float d[4], const uint32_t a[4], const uint32_t b[2]) {
    asm volatile("mma.sync.aligned.m16n8k16.row.col.f32.f16.f16.f32 "
                 "{%0,%1,%2,%3}, {%4,%5,%6,%7}, {%8,%9}, {%0,%1,%2,%3};"
                 : "+f"(d[0]), "+f"(d[1]), "+f"(d[2]), "+f"(d[3])
                 : "r"(a[0]), "r"(a[1]), "r"(a[2]), "r"(a[3]), "r"(b[0]), "r"(b[1]));
}

// ---------------- Kernel: fp32 -> fp16 (hi, optional lo) -------------------
__global__ __launch_bounds__(256)
void k_split(const float* __restrict__ src, int which, int n4) {
    int i = blockIdx.x * 256 + threadIdx.x;
    if (i >= n4) return;
    float4 v = ((const float4*)src)[i];
    __half h0 = __float2half(v.x), h1 = __float2half(v.y);
    __half h2 = __float2half(v.z), h3 = __float2half(v.w);
    union { __half h[4]; uint2 u; } ph;
    ph.h[0] = h0; ph.h[1] = h1; ph.h[2] = h2; ph.h[3] = h3;
    if (which) {                                   // W: hi only
        *(uint2*)(g_Wh + (size_t)i * 4) = ph.u;
    } else {                                       // x: hi + lo
        *(uint2*)(g_xh + (size_t)i * 4) = ph.u;
        union { __half h[4]; uint2 u; } pl;
        pl.h[0] = __float2half(v.x - __half2float(h0));
        pl.h[1] = __float2half(v.y - __half2float(h1));
        pl.h[2] = __float2half(v.z - __half2float(h2));
        pl.h[3] = __float2half(v.w - __half2float(h3));
        *(uint2*)(g_xl + (size_t)i * 4) = pl.u;
    }
}

// ---------------- mma.sync fp16 2-pass GEMM --------------------------------
// D[m,n] = sum_k A[m,k]*B[n,k];  A plain fp16, B = hi+lo fp16 (2 MMA passes).
// CTA 128x128, 8 warps (2m x 4n), K-chunk 64, 2-stage cp.async.
// Stage: A 16K | Bhi 16K | Blo 16K = 48K.  128B swizzled rows (64 fp16 = k chunk).
// mode 0: qkv (A=W, B=x; m0<512 -> fused q-softmax -> fp16 g_qh, else g_kv fp32)
// mode 1: out (A=q, B=M; D+bias -> y fp32)
#define STAGE_B  49152
#define SMEM_MM  (2 * STAGE_B)

__global__ __launch_bounds__(256, 2)
void k_mm(float* __restrict__ Cout, const float* __restrict__ bias, int mode) {
    extern __shared__ char smem[];
    const int tid  = threadIdx.x;
    const int wid  = tid >> 5, lane = tid & 31;
    const int wm   = wid & 1;          // m offset wm*64
    const int wn   = wid >> 1;         // n offset wn*32
    const int b    = blockIdx.z;
    const int m0   = blockIdx.y * 128;
    const int n0   = blockIdx.x * 128;

    const uint32_t smbase = smem_u32(smem);

    const __half *Ah, *Bh, *Bl;
    if (mode == 0) {
        Ah = g_Wh + (size_t)m0 * D_;
        Bh = g_xh + ((size_t)b * L_ + n0) * D_;  Bl = g_xl + ((size_t)b * L_ + n0) * D_;
    } else {
        Ah = g_qh + ((size_t)b * L_ + m0) * D_;
        Bh = g_Mh + ((size_t)b * D_ + n0) * D_;  Bl = g_Ml + ((size_t)b * D_ + n0) * D_;
    }

    // stage loader: 3072 cp16 / 256 threads = 12 each
    auto load_stage = [&](int s, int d0) {
        uint32_t base = smbase + s * STAGE_B;
#pragma unroll
        for (int i = 0; i < 12; i++) {
            int id = i * 256 + tid;                // 0..3071
            int pl = id >> 10;                     // 0=A, 1=Bhi, 2=Blo
            int r  = (id >> 3) & 127;
            int u  = id & 7;                       // 16B unit within 128B row
            const __half* src = (pl == 0 ? Ah : (pl == 1 ? Bh : Bl)) + (size_t)r * D_ + d0 + u * 8;
            cp16(base + pl * 16384 + SWZ128((uint32_t)(r * 128 + u * 16)), src);
        }
        CP_COMMIT();
    };

    float acc[4][4][4];
#pragma unroll
    for (int i = 0; i < 4; i++)
#pragma unroll
        for (int j = 0; j < 4; j++)
#pragma unroll
            for (int k = 0; k < 4; k++) acc[i][j][k] = 0.f;

    const uint32_t a_row = wm * 64 + (lane & 15);
    const uint32_t a_ub  = (lane >> 4);            // 0..1
    const uint32_t b_row = wn * 32 + (lane & 7);
    const uint32_t b_ub  = (lane >> 3) & 1;

    load_stage(0, 0);

    for (int kc = 0; kc < 8; kc++) {
        int s = kc & 1;
        if (kc + 1 < 8) {
            load_stage(s ^ 1, (kc + 1) * 64);
            asm volatile("cp.async.wait_group 1;");
        } else {
            asm volatile("cp.async.wait_group 0;");
        }
        __syncthreads();

        uint32_t smA = smbase + s * STAGE_B;
        uint32_t smBh = smA + 16384, smBl = smA + 32768;
#pragma unroll
        for (int sl = 0; sl < 4; sl++) {           // k16 slices within 64-chunk
            uint32_t ah[4][4];
#pragma unroll
            for (int mt = 0; mt < 4; mt++)
                ldsm_x4(ah[mt], smA + SWZ128((a_row + mt * 16) * 128 + (sl * 2 + a_ub) * 16));
#pragma unroll
            for (int nt = 0; nt < 4; nt++) {
                uint32_t off = SWZ128((b_row + nt * 8) * 128 + (sl * 2 + b_ub) * 16);
                uint32_t bh[2], bl[2];
                ldsm_x2(bh, smBh + off);
                ldsm_x2(bl, smBl + off);
#pragma unroll
                for (int mt = 0; mt < 4; mt++) {
                    mma_f16(acc[mt][nt], ah[mt], bh);
                    mma_f16(acc[mt][nt], ah[mt], bl);
                }
            }
        }
        __syncthreads();
    }

    // ---- epilogue via smem, two 64-col halves ----
    float* ep = (float*)smem;                      // [128][65]
    float* inv_s = ep + 128 * 65;                  // [2][64]
    for (int p = 0; p < 2; p++) {
        if ((wn >> 1) == p) {
            int cb = (wn & 1) * 32;
#pragma unroll
            for (int mt = 0; mt < 4; mt++)
#pragma unroll
                for (int nt = 0; nt < 4; nt++) {
                    int row = wm * 64 + mt * 16 + (lane >> 2);
                    int col = cb + nt * 8 + (lane & 3) * 2;
                    ep[row * 65 + col]           = acc[mt][nt][0];
                    ep[row * 65 + col + 1]       = acc[mt][nt][1];
                    ep[(row + 8) * 65 + col]     = acc[mt][nt][2];
                    ep[(row + 8) * 65 + col + 1] = acc[mt][nt][3];
                }
        }
        __syncthreads();
        int c0 = p * 64;
        if (mode == 0 && m0 < 512) {
            // fused q-softmax over channel dim (64 rows/head, 2 heads/tile)
            if (tid < 128) {
                int c  = tid & 63;
                int r0 = (tid >> 6) * 64;
                float mx = -3.0e38f;
#pragma unroll 8
                for (int r = 0; r < 64; r++) mx = fmaxf(mx, ep[(r0 + r) * 65 + c]);
                float s = 0.f;
#pragma unroll 8
                for (int r = 0; r < 64; r++) {
                    float e = expf(ep[(r0 + r) * 65 + c] - mx);
                    ep[(r0 + r) * 65 + c] = e;
                    s += e;
                }
                inv_s[tid] = 1.0f / s;
            }
            __syncthreads();
            // write fp16 q transposed: g_qh[b][l][channel]
#pragma unroll
            for (int i = 0; i < 8; i++) {
                int id = tid + 256 * i;
                int c = id >> 5, mg = id & 31;
                float inv = inv_s[(mg >> 4) * 64 + c];
                union { __half h[4]; uint2 u; } ph;
                ph.h[0] = __float2half(ep[(mg * 4 + 0) * 65 + c] * inv);
                ph.h[1] = __float2half(ep[(mg * 4 + 1) * 65 + c] * inv);
                ph.h[2] = __float2half(ep[(mg * 4 + 2) * 65 + c] * inv);
                ph.h[3] = __float2half(ep[(mg * 4 + 3) * 65 + c] * inv);
                *(uint2*)(g_qh + ((size_t)b * L_ + n0 + c0 + c) * D_ + m0 + mg * 4) = ph.u;
            }
        } else {
            float* dst; int ldc;
            if (mode == 0) { dst = g_kv + ((size_t)b * 1024 + (m0 - 512)) * L_; ldc = L_; }
            else           { dst = Cout + ((size_t)b * L_ + m0) * D_;           ldc = D_; }
#pragma unroll
            for (int i = 0; i < 8; i++) {
                int id = tid + 256 * i;
                int m = id >> 4, g = id & 15;
                float4 v;
                v.x = ep[m * 65 + g * 4 + 0];
                v.y = ep[m * 65 + g * 4 + 1];
                v.z = ep[m * 65 + g * 4 + 2];
                v.w = ep[m * 65 + g * 4 + 3];
                if (mode == 1) {
                    v.x += __ldg(bias + n0 + c0 + g * 4 + 0);
                    v.y += __ldg(bias + n0 + c0 + g * 4 + 1);
                    v.z += __ldg(bias + n0 + c0 + g * 4 + 2);
                    v.w += __ldg(bias + n0 + c0 + g * 4 + 3);
                }
                *(float4*)(dst + (size_t)m * ldc + n0 + c0 + g * 4) = v;
            }
        }
        __syncthreads();
    }
}

// ---------------- softmax over L for k rows (register-cached) --------------
__global__ __launch_bounds__(256)
void k_softmax_rows() {
    const int r = blockIdx.x, b = blockIdx.y;
    float* row = g_kv + ((size_t)b * 1024 + r) * L_;
    const int tid = threadIdx.x;
    __shared__ float red[8], bc[2];

    float4 v[4];
    float mx = -3.0e38f;
#pragma unroll
    for (int j = 0; j < 4; j++) {
        v[j] = ((const float4*)row)[tid + 256 * j];
        mx = fmaxf(mx, fmaxf(fmaxf(v[j].x, v[j].y), fmaxf(v[j].z, v[j].w)));
    }
#pragma unroll
    for (int o = 16; o; o >>= 1) mx = fmaxf(mx, __shfl_xor_sync(0xffffffffu, mx, o));
    if ((tid & 31) == 0) red[tid >> 5] = mx;
    __syncthreads();
    if (tid < 32) {
        float m2 = (tid < 8) ? red[tid] : -3.0e38f;
#pragma unroll
        for (int o = 4; o; o >>= 1) m2 = fmaxf(m2, __shfl_xor_sync(0xffffffffu, m2, o));
        if (tid == 0) bc[0] = m2;
    }
    __syncthreads();
    const float m = bc[0];

    float s = 0.f;
#pragma unroll
    for (int j = 0; j < 4; j++) {
        v[j].x = expf(v[j].x - m); v[j].y = expf(v[j].y - m);
        v[j].z = expf(v[j].z - m); v[j].w = expf(v[j].w - m);
        s += (v[j].x + v[j].y) + (v[j].z + v[j].w);
    }
#pragma unroll
    for (int o = 16; o; o >>= 1) s += __shfl_xor_sync(0xffffffffu, s, o);
    if ((tid & 31) == 0) red[tid >> 5] = s;
    __syncthreads();
    if (tid < 32) {
        float s2 = (tid < 8) ? red[tid] : 0.f;
#pragma unroll
        for (int o = 4; o; o >>= 1) s2 += __shfl_xor_sync(0xffffffffu, s2, o);
        if (tid == 0) bc[1] = s2;
    }
    __syncthreads();
    const float inv = 1.0f / bc[1];
#pragma unroll
    for (int j = 0; j < 4; j++) {
        v[j].x *= inv; v[j].y *= inv; v[j].z *= inv; v[j].w *= inv;
        ((float4*)row)[tid + 256 * j] = v[j];
    }
}

// ---------------- context partials: ctx[d,e] = sum_n k[d,n] v[e,n] ---------
__global__ __launch_bounds__(256)
void k_ctx() {
    const int bh = blockIdx.x, sp = blockIdx.y;
    const int b = bh >> 3, h = bh & 7;
    const float* kbase = g_kv + ((size_t)b * 1024 + h * CH) * L_;
    const float* vbase = g_kv + ((size_t)b * 1024 + 512 + h * CH) * L_;

    __shared__ float ks[64][65];
    __shared__ float vs[64][65];
    const int tid = threadIdx.x;
    const int tx = tid & 15, ty = tid >> 4;

    float acc[4][4];
#pragma unroll
    for (int i = 0; i < 4; i++)
#pragma unroll
        for (int j = 0; j < 4; j++) acc[i][j] = 0.f;

    for (int chn = 0; chn < 8; chn++) {
        int n0 = sp * 512 + chn * 64;
#pragma unroll
        for (int i = 0; i < 4; i++) {
            int id = tid + 256 * i;
            int row = id >> 4, col = (id & 15) * 4;
            float4 kv = *(const float4*)(kbase + (size_t)row * L_ + n0 + col);
            ks[row][col+0]=kv.x; ks[row][col+1]=kv.y; ks[row][col+2]=kv.z; ks[row][col+3]=kv.w;
            float4 vv = *(const float4*)(vbase + (size_t)row * L_ + n0 + col);
            vs[row][col+0]=vv.x; vs[row][col+1]=vv.y; vs[row][col+2]=vv.z; vs[row][col+3]=vv.w;
        }
        __syncthreads();
#pragma unroll 4
        for (int nn = 0; nn < 64; nn++) {
            float kr[4], vr[4];
#pragma unroll
            for (int i = 0; i < 4; i++) kr[i] = ks[ty * 4 + i][nn];
#pragma unroll
            for (int j = 0; j < 4; j++) vr[j] = vs[tx + 16 * j][nn];
#pragma unroll
            for (int i = 0; i < 4; i++)
#pragma unroll
                for (int j = 0; j < 4; j++) acc[i][j] = fmaf(kr[i], vr[j], acc[i][j]);
        }
        __syncthreads();
    }
    float* out = g_ctxp + (size_t)(bh * 8 + sp) * 4096;
#pragma unroll
    for (int i = 0; i < 4; i++)
#pragma unroll
        for (int j = 0; j < 4; j++)
            out[(size_t)(ty * 4 + i) * 64 + tx + 16 * j] = acc[i][j];
}

// ---------------- reduce ctx + M = Wout-contract, emit fp16 hi/lo ----------
__global__ __launch_bounds__(256)
void k_M(const float* __restrict__ Wout) {
    const int bh = blockIdx.x;
    const int b = bh >> 3, h = bh & 7;
    __shared__ float ctxs[64][65];
    const int tid = threadIdx.x;

    for (int e0 = tid; e0 < 4096; e0 += 256) {
        float sum = 0.f;
        const float* p = g_ctxp + (size_t)bh * 8 * 4096 + e0;
#pragma unroll
        for (int s = 0; s < 8; s++) sum += p[(size_t)s * 4096];
        ctxs[e0 >> 6][e0 & 63] = sum;
    }
    __syncthreads();

    const int d = tid & 63, dq = tid >> 6;
    for (int dout = dq; dout < D_; dout += 4) {
        const float* wrow = Wout + (size_t)dout * D_ + h * CH;
        float sum = 0.f;
#pragma unroll
        for (int e = 0; e < CH; e++) sum = fmaf(__ldg(wrow + e), ctxs[d][e], sum);
        size_t o = (size_t)b * D_ * D_ + (size_t)dout * D_ + h * CH + d;
        __half hi = __float2half(sum);
        g_Mh[o] = hi;
        g_Ml[o] = __float2half(sum - __half2float(hi));
    }
}

// ---------------------------------------------------------------------------
extern "C" void kernel_launch(void* const* d_in, const int* in_sizes, int n_in,
                              void* d_out, int out_size) {
    const float* x    = (const float*)d_in[0];
    const float* Wqkv = (const float*)d_in[1];
    const float* Wout = (const float*)d_in[2];
    const float* bout = (const float*)d_in[3];
    float* y = (float*)d_out;

    cudaFuncSetAttribute(k_mm, cudaFuncAttributeMaxDynamicSharedMemorySize, SMEM_MM);

    int n4x = B_ * L_ * D_ / 4;
    int n4w = O3 * D_ / 4;
    k_split<<<(n4x + 255) / 256, 256>>>(x, 0, n4x);
    k_split<<<(n4w + 255) / 256, 256>>>(Wqkv, 1, n4w);

    k_mm<<<dim3(32, 12, B_), 256, SMEM_MM>>>(nullptr, nullptr, 0);    // qkv
    k_softmax_rows<<<dim3(512, B_), 256>>>();
    k_ctx<<<dim3(64, 8), 256>>>();
    k_M<<<64, 256>>>(Wout);
    k_mm<<<dim3(4, 32, B_), 256, SMEM_MM>>>(y, bout, 1);              // out
}

// round 10
// speedup vs baseline: 2.5247x; 1.2283x over previous
#include <cuda_runtime.h>
#include <cuda_fp16.h>
#include <cstdint>
#include <math.h>

#define B_  8
#define L_  4096
#define D_  512
#define H_  8
#define CH  64
#define O3  1536

// ---------------- scratch (__device__ globals; no allocs allowed) ----------
__device__ float g_kv[(size_t)B_ * 1024 * L_];                 // k rows 0..511, v rows 512..1023, [b][row][L]
__device__ float g_ctxp[64 * 8 * 64 * 64];                     // [bh][split][d][e]
__device__ __half g_Wh[(size_t)O3 * D_];                       // W fp16
__device__ __half g_xh[(size_t)B_ * L_ * D_];                  // x fp16
__device__ __half g_qh[(size_t)B_ * L_ * D_];                  // q fp16 [b][l][c]
__device__ __half g_Mh[(size_t)B_ * D_ * D_];                  // M fp16

// ---------------- PTX helpers ---------------------------------------------
__device__ __forceinline__ uint32_t smem_u32(const void* p) {
    uint32_t a;
    asm("{ .reg .u64 t; cvta.to.shared.u64 t, %1; cvt.u32.u64 %0, t; }" : "=r"(a) : "l"(p));
    return a;
}
#define SWZ128(b) ((b) ^ (((b) >> 3) & 0x70))

__device__ __forceinline__ void cp16(uint32_t dst, const void* src) {
    asm volatile("cp.async.cg.shared.global [%0], [%1], 16;" :: "r"(dst), "l"(src));
}
#define CP_COMMIT() asm volatile("cp.async.commit_group;")

__device__ __forceinline__ void ldsm_x4(uint32_t r[4], uint32_t a) {
    asm volatile("ldmatrix.sync.aligned.m8n8.x4.shared.b16 {%0,%1,%2,%3}, [%4];"
                 : "=r"(r[0]), "=r"(r[1]), "=r"(r[2]), "=r"(r[3]) : "r"(a));
}
__device__ __forceinline__ void ldsm_x2(uint32_t r[2], uint32_t a) {
    asm volatile("ldmatrix.sync.aligned.m8n8.x2.shared.b16 {%0,%1}, [%2];"
                 : "=r"(r[0]), "=r"(r[1]) : "r"(a));
}
__device__ __forceinline__ void mma_f16(float d[4], const uint32_t a[4], const uint32_t b[2]) {
    asm volatile("mma.sync.aligned.m16n8k16.row.col.f32.f16.f16.f32 "
                 "{%0,%1,%2,%3}, {%4,%5,%6,%7}, {%8,%9}, {%0,%1,%2,%3};"
                 : "+f"(d[0]), "+f"(d[1]), "+f"(d[2]), "+f"(d[3])
                 : "r"(a[0]), "r"(a[1]), "r"(a[2]), "r"(a[3]), "r"(b[0]), "r"(b[1]));
}

// ---------------- Kernel: fp32 -> fp16 -------------------------------------
__global__ __launch_bounds__(256)
void k_split(const float* __restrict__ src, int which, int n4) {
    int i = blockIdx.x * 256 + threadIdx.x;
    if (i >= n4) return;
    float4 v = ((const float4*)src)[i];
    union { __half h[4]; uint2 u; } ph;
    ph.h[0] = __float2half(v.x); ph.h[1] = __float2half(v.y);
    ph.h[2] = __float2half(v.z); ph.h[3] = __float2half(v.w);
    __half* dst = which ? g_Wh : g_xh;
    *(uint2*)(dst + (size_t)i * 4) = ph.u;
}

// ---------------- mma.sync fp16 single-pass GEMM ---------------------------
// D[m,n] = sum_k A[m,k]*B[n,k]; both plain fp16, fp32 accum.
// CTA 128x128, 8 warps (2m x 4n), K-chunk 64, 2-stage cp.async.
// Stage: A 16K | B 16K = 32K.  128B swizzled rows (64 fp16 = K chunk).
// mode 0: qkv (A=W, B=x; m0<512 -> fused q-softmax -> fp16 g_qh, else g_kv fp32)
// mode 1: out (A=q, B=M; D+bias -> y fp32)
#define STAGE_B  32768
#define SMEM_MM  (2 * STAGE_B)

__global__ __launch_bounds__(256, 2)
void k_mm(float* __restrict__ Cout, const float* __restrict__ bias, int mode) {
    extern __shared__ char smem[];
    const int tid  = threadIdx.x;
    const int wid  = tid >> 5, lane = tid & 31;
    const int wm   = wid & 1;          // m offset wm*64
    const int wn   = wid >> 1;         // n offset wn*32
    const int b    = blockIdx.z;
    const int m0   = blockIdx.y * 128;
    const int n0   = blockIdx.x * 128;

    const uint32_t smbase = smem_u32(smem);

    const __half *Ah, *Bh;
    if (mode == 0) {
        Ah = g_Wh + (size_t)m0 * D_;
        Bh = g_xh + ((size_t)b * L_ + n0) * D_;
    } else {
        Ah = g_qh + ((size_t)b * L_ + m0) * D_;
        Bh = g_Mh + ((size_t)b * D_ + n0) * D_;
    }

    // stage loader: 2048 cp16 / 256 threads = 8 each
    auto load_stage = [&](int s, int d0) {
        uint32_t base = smbase + s * STAGE_B;
#pragma unroll
        for (int i = 0; i < 8; i++) {
            int id = i * 256 + tid;                // 0..2047
            int pl = id >> 10;                     // 0=A, 1=B
            int r  = (id >> 3) & 127;
            int u  = id & 7;                       // 16B unit within 128B row
            const __half* src = (pl ? Bh : Ah) + (size_t)r * D_ + d0 + u * 8;
            cp16(base + pl * 16384 + SWZ128((uint32_t)(r * 128 + u * 16)), src);
        }
        CP_COMMIT();
    };

    float acc[4][4][4];
#pragma unroll
    for (int i = 0; i < 4; i++)
#pragma unroll
        for (int j = 0; j < 4; j++)
#pragma unroll
            for (int k = 0; k < 4; k++) acc[i][j][k] = 0.f;

    const uint32_t a_row = wm * 64 + (lane & 15);
    const uint32_t a_ub  = (lane >> 4);            // 0..1
    const uint32_t b_row = wn * 32 + (lane & 7);
    const uint32_t b_ub  = (lane >> 3) & 1;

    load_stage(0, 0);

    for (int kc = 0; kc < 8; kc++) {
        int s = kc & 1;
        if (kc + 1 < 8) {
            load_stage(s ^ 1, (kc + 1) * 64);
            asm volatile("cp.async.wait_group 1;");
        } else {
            asm volatile("cp.async.wait_group 0;");
        }
        __syncthreads();

        uint32_t smA = smbase + s * STAGE_B;
        uint32_t smB = smA + 16384;
#pragma unroll
        for (int sl = 0; sl < 4; sl++) {           // k16 slices within 64-chunk
            uint32_t ah[4][4];
#pragma unroll
            for (int mt = 0; mt < 4; mt++)
                ldsm_x4(ah[mt], smA + SWZ128((a_row + mt * 16) * 128 + (sl * 2 + a_ub) * 16));
#pragma unroll
            for (int nt = 0; nt < 4; nt++) {
                uint32_t bh[2];
                ldsm_x2(bh, smB + SWZ128((b_row + nt * 8) * 128 + (sl * 2 + b_ub) * 16));
#pragma unroll
                for (int mt = 0; mt < 4; mt++)
                    mma_f16(acc[mt][nt], ah[mt], bh);
            }
        }
        __syncthreads();
    }

    // ---- epilogue via smem, two 64-col halves ----
    float* ep = (float*)smem;                      // [128][65]
    float* inv_s = ep + 128 * 65;                  // [2][64]
    for (int p = 0; p < 2; p++) {
        if ((wn >> 1) == p) {
            int cb = (wn & 1) * 32;
#pragma unroll
            for (int mt = 0; mt < 4; mt++)
#pragma unroll
                for (int nt = 0; nt < 4; nt++) {
                    int row = wm * 64 + mt * 16 + (lane >> 2);
                    int col = cb + nt * 8 + (lane & 3) * 2;
                    ep[row * 65 + col]           = acc[mt][nt][0];
                    ep[row * 65 + col + 1]       = acc[mt][nt][1];
                    ep[(row + 8) * 65 + col]     = acc[mt][nt][2];
                    ep[(row + 8) * 65 + col + 1] = acc[mt][nt][3];
                }
        }
        __syncthreads();
        int c0 = p * 64;
        if (mode == 0 && m0 < 512) {
            // fused q-softmax over channel dim (64 rows/head, 2 heads/tile)
            if (tid < 128) {
                int c  = tid & 63;
                int r0 = (tid >> 6) * 64;
                float mx = -3.0e38f;
#pragma unroll 8
                for (int r = 0; r < 64; r++) mx = fmaxf(mx, ep[(r0 + r) * 65 + c]);
                float s = 0.f;
#pragma unroll 8
                for (int r = 0; r < 64; r++) {
                    float e = expf(ep[(r0 + r) * 65 + c] - mx);
                    ep[(r0 + r) * 65 + c] = e;
                    s += e;
                }
                inv_s[tid] = 1.0f / s;
            }
            __syncthreads();
            // write fp16 q transposed: g_qh[b][l][channel]
#pragma unroll
            for (int i = 0; i < 8; i++) {
                int id = tid + 256 * i;
                int c = id >> 5, mg = id & 31;
                float inv = inv_s[(mg >> 4) * 64 + c];
                union { __half h[4]; uint2 u; } ph;
                ph.h[0] = __float2half(ep[(mg * 4 + 0) * 65 + c] * inv);
                ph.h[1] = __float2half(ep[(mg * 4 + 1) * 65 + c] * inv);
                ph.h[2] = __float2half(ep[(mg * 4 + 2) * 65 + c] * inv);
                ph.h[3] = __float2half(ep[(mg * 4 + 3) * 65 + c] * inv);
                *(uint2*)(g_qh + ((size_t)b * L_ + n0 + c0 + c) * D_ + m0 + mg * 4) = ph.u;
            }
        } else {
            float* dst; int ldc;
            if (mode == 0) { dst = g_kv + ((size_t)b * 1024 + (m0 - 512)) * L_; ldc = L_; }
            else           { dst = Cout + ((size_t)b * L_ + m0) * D_;           ldc = D_; }
#pragma unroll
            for (int i = 0; i < 8; i++) {
                int id = tid + 256 * i;
                int m = id >> 4, g = id & 15;
                float4 v;
                v.x = ep[m * 65 + g * 4 + 0];
                v.y = ep[m * 65 + g * 4 + 1];
                v.z = ep[m * 65 + g * 4 + 2];
                v.w = ep[m * 65 + g * 4 + 3];
                if (mode == 1) {
                    v.x += __ldg(bias + n0 + c0 + g * 4 + 0);
                    v.y += __ldg(bias + n0 + c0 + g * 4 + 1);
                    v.z += __ldg(bias + n0 + c0 + g * 4 + 2);
                    v.w += __ldg(bias + n0 + c0 + g * 4 + 3);
                }
                *(float4*)(dst + (size_t)m * ldc + n0 + c0 + g * 4) = v;
            }
        }
        __syncthreads();
    }
}

// ---------------- softmax over L for k rows (register-cached) --------------
__global__ __launch_bounds__(256)
void k_softmax_rows() {
    const int r = blockIdx.x, b = blockIdx.y;
    float* row = g_kv + ((size_t)b * 1024 + r) * L_;
    const int tid = threadIdx.x;
    __shared__ float red[8], bc[2];

    float4 v[4];
    float mx = -3.0e38f;
#pragma unroll
    for (int j = 0; j < 4; j++) {
        v[j] = ((const float4*)row)[tid + 256 * j];
        mx = fmaxf(mx, fmaxf(fmaxf(v[j].x, v[j].y), fmaxf(v[j].z, v[j].w)));
    }
#pragma unroll
    for (int o = 16; o; o >>= 1) mx = fmaxf(mx, __shfl_xor_sync(0xffffffffu, mx, o));
    if ((tid & 31) == 0) red[tid >> 5] = mx;
    __syncthreads();
    if (tid < 32) {
        float m2 = (tid < 8) ? red[tid] : -3.0e38f;
#pragma unroll
        for (int o = 4; o; o >>= 1) m2 = fmaxf(m2, __shfl_xor_sync(0xffffffffu, m2, o));
        if (tid == 0) bc[0] = m2;
    }
    __syncthreads();
    const float m = bc[0];

    float s = 0.f;
#pragma unroll
    for (int j = 0; j < 4; j++) {
        v[j].x = expf(v[j].x - m); v[j].y = expf(v[j].y - m);
        v[j].z = expf(v[j].z - m); v[j].w = expf(v[j].w - m);
        s += (v[j].x + v[j].y) + (v[j].z + v[j].w);
    }
#pragma unroll
    for (int o = 16; o; o >>= 1) s += __shfl_xor_sync(0xffffffffu, s, o);
    if ((tid & 31) == 0) red[tid >> 5] = s;
    __syncthreads();
    if (tid < 32) {
        float s2 = (tid < 8) ? red[tid] : 0.f;
#pragma unroll
        for (int o = 4; o; o >>= 1) s2 += __shfl_xor_sync(0xffffffffu, s2, o);
        if (tid == 0) bc[1] = s2;
    }
    __syncthreads();
    const float inv = 1.0f / bc[1];
#pragma unroll
    for (int j = 0; j < 4; j++) {
        v[j].x *= inv; v[j].y *= inv; v[j].z *= inv; v[j].w *= inv;
        ((float4*)row)[tid + 256 * j] = v[j];
    }
}

// ---------------- context partials: ctx[d,e] = sum_n k[d,n] v[e,n] ---------
__global__ __launch_bounds__(256)
void k_ctx() {
    const int bh = blockIdx.x, sp = blockIdx.y;
    const int b = bh >> 3, h = bh & 7;
    const float* kbase = g_kv + ((size_t)b * 1024 + h * CH) * L_;
    const float* vbase = g_kv + ((size_t)b * 1024 + 512 + h * CH) * L_;

    __shared__ float ks[64][65];
    __shared__ float vs[64][65];
    const int tid = threadIdx.x;
    const int tx = tid & 15, ty = tid >> 4;

    float acc[4][4];
#pragma unroll
    for (int i = 0; i < 4; i++)
#pragma unroll
        for (int j = 0; j < 4; j++) acc[i][j] = 0.f;

    for (int chn = 0; chn < 8; chn++) {
        int n0 = sp * 512 + chn * 64;
#pragma unroll
        for (int i = 0; i < 4; i++) {
            int id = tid + 256 * i;
            int row = id >> 4, col = (id & 15) * 4;
            float4 kv = *(const float4*)(kbase + (size_t)row * L_ + n0 + col);
            ks[row][col+0]=kv.x; ks[row][col+1]=kv.y; ks[row][col+2]=kv.z; ks[row][col+3]=kv.w;
            float4 vv = *(const float4*)(vbase + (size_t)row * L_ + n0 + col);
            vs[row][col+0]=vv.x; vs[row][col+1]=vv.y; vs[row][col+2]=vv.z; vs[row][col+3]=vv.w;
        }
        __syncthreads();
#pragma unroll 4
        for (int nn = 0; nn < 64; nn++) {
            float kr[4], vr[4];
#pragma unroll
            for (int i = 0; i < 4; i++) kr[i] = ks[ty * 4 + i][nn];
#pragma unroll
            for (int j = 0; j < 4; j++) vr[j] = vs[tx + 16 * j][nn];
#pragma unroll
            for (int i = 0; i < 4; i++)
#pragma unroll
                for (int j = 0; j < 4; j++) acc[i][j] = fmaf(kr[i], vr[j], acc[i][j]);
        }
        __syncthreads();
    }
    float* out = g_ctxp + (size_t)(bh * 8 + sp) * 4096;
#pragma unroll
    for (int i = 0; i < 4; i++)
#pragma unroll
        for (int j = 0; j < 4; j++)
            out[(size_t)(ty * 4 + i) * 64 + tx + 16 * j] = acc[i][j];
}

// ---------------- reduce ctx + M = Wout-contract, emit fp16 ----------------
__global__ __launch_bounds__(256)
void k_M(const float* __restrict__ Wout) {
    const int bh = blockIdx.x;
    const int b = bh >> 3, h = bh & 7;
    __shared__ float ctxs[64][65];
    const int tid = threadIdx.x;

    for (int e0 = tid; e0 < 4096; e0 += 256) {
        float sum = 0.f;
        const float* p = g_ctxp + (size_t)bh * 8 * 4096 + e0;
#pragma unroll
        for (int s = 0; s < 8; s++) sum += p[(size_t)s * 4096];
        ctxs[e0 >> 6][e0 & 63] = sum;
    }
    __syncthreads();

    const int d = tid & 63, dq = tid >> 6;
    for (int dout = dq; dout < D_; dout += 4) {
        const float* wrow = Wout + (size_t)dout * D_ + h * CH;
        float sum = 0.f;
#pragma unroll
        for (int e = 0; e < CH; e++) sum = fmaf(__ldg(wrow + e), ctxs[d][e], sum);
        g_Mh[(size_t)b * D_ * D_ + (size_t)dout * D_ + h * CH + d] = __float2half(sum);
    }
}

// ---------------------------------------------------------------------------
extern "C" void kernel_launch(void* const* d_in, const int* in_sizes, int n_in,
                              void* d_out, int out_size) {
    const float* x    = (const float*)d_in[0];
    const float* Wqkv = (const float*)d_in[1];
    const float* Wout = (const float*)d_in[2];
    const float* bout = (const float*)d_in[3];
    float* y = (float*)d_out;

    cudaFuncSetAttribute(k_mm, cudaFuncAttributeMaxDynamicSharedMemorySize, SMEM_MM);

    int n4x = B_ * L_ * D_ / 4;
    int n4w = O3 * D_ / 4;
    k_split<<<(n4x + 255) / 256, 256>>>(x, 0, n4x);
    k_split<<<(n4w + 255) / 256, 256>>>(Wqkv, 1, n4w);

    k_mm<<<dim3(32, 12, B_), 256, SMEM_MM>>>(nullptr, nullptr, 0);    // qkv
    k_softmax_rows<<<dim3(512, B_), 256>>>();
    k_ctx<<<dim3(64, 8), 256>>>();
    k_M<<<64, 256>>>(Wout);
    k_mm<<<dim3(4, 32, B_), 256, SMEM_MM>>>(y, bout, 1);              // out
}

// round 12
// speedup vs baseline: 2.6198x; 1.0377x over previous
#include <cuda_runtime.h>
#include <cuda_fp16.h>
#include <cstdint>
#include <math.h>

#define B_  8
#define L_  4096
#define D_  512
#define H_  8
#define CH  64
#define O3  1536

// ---------------- scratch (__device__ globals; no allocs allowed) ----------
__device__ float g_ctxp[64 * 8 * 64 * 64];                     // [bh][split][d][e]
__device__ __half g_Wh[(size_t)O3 * D_];                       // W fp16
__device__ __half g_xh[(size_t)B_ * L_ * D_];                  // x fp16
__device__ __half g_qh[(size_t)B_ * L_ * D_];                  // q fp16 [b][l][c]
__device__ __half g_kh[(size_t)B_ * D_ * L_];                  // k fp16 [b][row][L]
__device__ __half g_vh[(size_t)B_ * D_ * L_];                  // v fp16 [b][row][L]
__device__ __half g_Mh[(size_t)B_ * D_ * D_];                  // M fp16

// ---------------- PTX helpers ---------------------------------------------
__device__ __forceinline__ uint32_t smem_u32(const void* p) {
    uint32_t a;
    asm("{ .reg .u64 t; cvta.to.shared.u64 t, %1; cvt.u32.u64 %0, t; }" : "=r"(a) : "l"(p));
    return a;
}
#define SWZ128(b) ((b) ^ (((b) >> 3) & 0x70))

__device__ __forceinline__ void cp16(uint32_t dst, const void* src) {
    asm volatile("cp.async.cg.shared.global [%0], [%1], 16;" :: "r"(dst), "l"(src));
}
#define CP_COMMIT() asm volatile("cp.async.commit_group;")

__device__ __forceinline__ void ldsm_x4(uint32_t r[4], uint32_t a) {
    asm volatile("ldmatrix.sync.aligned.m8n8.x4.shared.b16 {%0,%1,%2,%3}, [%4];"
                 : "=r"(r[0]), "=r"(r[1]), "=r"(r[2]), "=r"(r[3]) : "r"(a));
}
__device__ __forceinline__ void ldsm_x2(uint32_t r[2], uint32_t a) {
    asm volatile("ldmatrix.sync.aligned.m8n8.x2.shared.b16 {%0,%1}, [%2];"
                 : "=r"(r[0]), "=r"(r[1]) : "r"(a));
}
__device__ __forceinline__ void mma_f16(float d[4], const uint32_t a[4], const uint32_t b[2]) {
    asm volatile("mma.sync.aligned.m16n8k16.row.col.f32.f16.f16.f32 "
                 "{%0,%1,%2,%3}, {%4,%5,%6,%7}, {%8,%9}, {%0,%1,%2,%3};"
                 : "+f"(d[0]), "+f"(d[1]), "+f"(d[2]), "+f"(d[3])
                 : "r"(a[0]), "r"(a[1]), "r"(a[2]), "r"(a[3]), "r"(b[0]), "r"(b[1]));
}

// ---------------- Kernel: fp32 -> fp16 -------------------------------------
__global__ __launch_bounds__(256)
void k_split(const float* __restrict__ src, int which, int n4) {
    int i = blockIdx.x * 256 + threadIdx.x;
    if (i >= n4) return;
    float4 v = ((const float4*)src)[i];
    union { __half h[4]; uint2 u; } ph;
    ph.h[0] = __float2half(v.x); ph.h[1] = __float2half(v.y);
    ph.h[2] = __float2half(v.z); ph.h[3] = __float2half(v.w);
    __half* dst = which ? g_Wh : g_xh;
    *(uint2*)(dst + (size_t)i * 4) = ph.u;
}

// ---------------- mma.sync fp16 single-pass GEMM, 3-stage ------------------
// D[m,n] = sum_k A[m,k]*B[n,k]; both fp16, fp32 accum.
// CTA 128x128, 8 warps (2m x 4n), K-chunk 64, 3-stage cp.async.
// mode 0: qkv (A=W, B=x; m0<512 -> fused q-softmax -> g_qh; else fp16 k/v)
// mode 1: out (A=q, B=M; D+bias -> y fp32)
#define STAGE_B  32768
#define SMEM_MM  (3 * STAGE_B)

__global__ __launch_bounds__(256, 2)
void k_mm(float* __restrict__ Cout, const float* __restrict__ bias, int mode) {
    extern __shared__ char smem[];
    const int tid  = threadIdx.x;
    const int wid  = tid >> 5, lane = tid & 31;
    const int wm   = wid & 1;          // m offset wm*64
    const int wn   = wid >> 1;         // n offset wn*32
    const int b    = blockIdx.z;
    const int m0   = blockIdx.y * 128;
    const int n0   = blockIdx.x * 128;

    const uint32_t smbase = smem_u32(smem);

    const __half *Ah, *Bh;
    if (mode == 0) {
        Ah = g_Wh + (size_t)m0 * D_;
        Bh = g_xh + ((size_t)b * L_ + n0) * D_;
    } else {
        Ah = g_qh + ((size_t)b * L_ + m0) * D_;
        Bh = g_Mh + ((size_t)b * D_ + n0) * D_;
    }

    auto load_stage = [&](int s, int d0) {
        uint32_t base = smbase + s * STAGE_B;
#pragma unroll
        for (int i = 0; i < 8; i++) {
            int id = i * 256 + tid;                // 0..2047
            int pl = id >> 10;                     // 0=A, 1=B
            int r  = (id >> 3) & 127;
            int u  = id & 7;
            const __half* src = (pl ? Bh : Ah) + (size_t)r * D_ + d0 + u * 8;
            cp16(base + pl * 16384 + SWZ128((uint32_t)(r * 128 + u * 16)), src);
        }
        CP_COMMIT();
    };

    float acc[4][4][4];
#pragma unroll
    for (int i = 0; i < 4; i++)
#pragma unroll
        for (int j = 0; j < 4; j++)
#pragma unroll
            for (int k = 0; k < 4; k++) acc[i][j][k] = 0.f;

    const uint32_t a_row = wm * 64 + (lane & 15);
    const uint32_t a_ub  = (lane >> 4);
    const uint32_t b_row = wn * 32 + (lane & 7);
    const uint32_t b_ub  = (lane >> 3) & 1;

    load_stage(0, 0);
    load_stage(1, 64);

#pragma unroll
    for (int kc = 0; kc < 8; kc++) {
        const int s = kc % 3;
        if (kc + 2 < 8) {
            load_stage((kc + 2) % 3, (kc + 2) * 64);
            asm volatile("cp.async.wait_group 2;");
        } else if (kc + 1 < 8) {
            asm volatile("cp.async.wait_group 1;");
        } else {
            asm volatile("cp.async.wait_group 0;");
        }
        __syncthreads();

        uint32_t smA = smbase + s * STAGE_B;
        uint32_t smB = smA + 16384;
#pragma unroll
        for (int sl = 0; sl < 4; sl++) {
            uint32_t ah[4][4];
#pragma unroll
            for (int mt = 0; mt < 4; mt++)
                ldsm_x4(ah[mt], smA + SWZ128((a_row + mt * 16) * 128 + (sl * 2 + a_ub) * 16));
#pragma unroll
            for (int nt = 0; nt < 4; nt++) {
                uint32_t bh[2];
                ldsm_x2(bh, smB + SWZ128((b_row + nt * 8) * 128 + (sl * 2 + b_ub) * 16));
#pragma unroll
                for (int mt = 0; mt < 4; mt++)
                    mma_f16(acc[mt][nt], ah[mt], bh);
            }
        }
        __syncthreads();
    }

    // ---- epilogue via smem, two 64-col halves ----
    float* ep = (float*)smem;                      // [128][65]
    float* inv_s = ep + 128 * 65;                  // [2][64]
    for (int p = 0; p < 2; p++) {
        if ((wn >> 1) == p) {
            int cb = (wn & 1) * 32;
#pragma unroll
            for (int mt = 0; mt < 4; mt++)
#pragma unroll
                for (int nt = 0; nt < 4; nt++) {
                    int row = wm * 64 + mt * 16 + (lane >> 2);
                    int col = cb + nt * 8 + (lane & 3) * 2;
                    ep[row * 65 + col]           = acc[mt][nt][0];
                    ep[row * 65 + col + 1]       = acc[mt][nt][1];
                    ep[(row + 8) * 65 + col]     = acc[mt][nt][2];
                    ep[(row + 8) * 65 + col + 1] = acc[mt][nt][3];
                }
        }
        __syncthreads();
        int c0 = p * 64;
        if (mode == 0 && m0 < 512) {
            // fused q-softmax over channel dim (64 rows/head, 2 heads/tile)
            if (tid < 128) {
                int c  = tid & 63;
                int r0 = (tid >> 6) * 64;
                float mx = -3.0e38f;
#pragma unroll 8
                for (int r = 0; r < 64; r++) mx = fmaxf(mx, ep[(r0 + r) * 65 + c]);
                float s = 0.f;
#pragma unroll 8
                for (int r = 0; r < 64; r++) {
                    float e = expf(ep[(r0 + r) * 65 + c] - mx);
                    ep[(r0 + r) * 65 + c] = e;
                    s += e;
                }
                inv_s[tid] = 1.0f / s;
            }
            __syncthreads();
#pragma unroll
            for (int i = 0; i < 8; i++) {
                int id = tid + 256 * i;
                int c = id >> 5, mg = id & 31;
                float inv = inv_s[(mg >> 4) * 64 + c];
                union { __half h[4]; uint2 u; } ph;
                ph.h[0] = __float2half(ep[(mg * 4 + 0) * 65 + c] * inv);
                ph.h[1] = __float2half(ep[(mg * 4 + 1) * 65 + c] * inv);
                ph.h[2] = __float2half(ep[(mg * 4 + 2) * 65 + c] * inv);
                ph.h[3] = __float2half(ep[(mg * 4 + 3) * 65 + c] * inv);
                *(uint2*)(g_qh + ((size_t)b * L_ + n0 + c0 + c) * D_ + m0 + mg * 4) = ph.u;
            }
        } else if (mode == 0) {
            // k / v -> fp16 [b][row][L]
            __half* dst = (m0 < 1024)
                ? g_kh + ((size_t)b * D_ + (m0 - 512))  * L_
                : g_vh + ((size_t)b * D_ + (m0 - 1024)) * L_;
#pragma unroll
            for (int i = 0; i < 8; i++) {
                int id = tid + 256 * i;
                int m = id >> 4, g = id & 15;
                union { __half h[4]; uint2 u; } ph;
                ph.h[0] = __float2half(ep[m * 65 + g * 4 + 0]);
                ph.h[1] = __float2half(ep[m * 65 + g * 4 + 1]);
                ph.h[2] = __float2half(ep[m * 65 + g * 4 + 2]);
                ph.h[3] = __float2half(ep[m * 65 + g * 4 + 3]);
                *(uint2*)(dst + (size_t)m * L_ + n0 + c0 + g * 4) = ph.u;
            }
        } else {
            float* dst = Cout + ((size_t)b * L_ + m0) * D_;
#pragma unroll
            for (int i = 0; i < 8; i++) {
                int id = tid + 256 * i;
                int m = id >> 4, g = id & 15;
                float4 v;
                v.x = ep[m * 65 + g * 4 + 0] + __ldg(bias + n0 + c0 + g * 4 + 0);
                v.y = ep[m * 65 + g * 4 + 1] + __ldg(bias + n0 + c0 + g * 4 + 1);
                v.z = ep[m * 65 + g * 4 + 2] + __ldg(bias + n0 + c0 + g * 4 + 2);
                v.w = ep[m * 65 + g * 4 + 3] + __ldg(bias + n0 + c0 + g * 4 + 3);
                *(float4*)(dst + (size_t)m * D_ + n0 + c0 + g * 4) = v;
            }
        }
        __syncthreads();
    }
}

// ---------------- softmax over L for k rows (fp16 storage) -----------------
__global__ __launch_bounds__(256)
void k_softmax_rows() {
    const int r = blockIdx.x, b = blockIdx.y;
    __half* row = g_kh + ((size_t)b * D_ + r) * L_;
    const int tid = threadIdx.x;
    __shared__ float red[8], bc[2];

    // 4096 halves = 512 uint4; 2 per thread (16 halves)
    union { uint4 u; __half2 h2[4]; } v[2];
    float f[16];
    float mx = -3.0e38f;
#pragma unroll
    for (int j = 0; j < 2; j++) {
        v[j].u = ((const uint4*)row)[tid + 256 * j];
#pragma unroll
        for (int q = 0; q < 4; q++) {
            float2 p = __half22float2(v[j].h2[q]);
            f[j * 8 + q * 2]     = p.x;
            f[j * 8 + q * 2 + 1] = p.y;
            mx = fmaxf(mx, fmaxf(p.x, p.y));
        }
    }
#pragma unroll
    for (int o = 16; o; o >>= 1) mx = fmaxf(mx, __shfl_xor_sync(0xffffffffu, mx, o));
    if ((tid & 31) == 0) red[tid >> 5] = mx;
    __syncthreads();
    if (tid < 32) {
        float m2 = (tid < 8) ? red[tid] : -3.0e38f;
#pragma unroll
        for (int o = 4; o; o >>= 1) m2 = fmaxf(m2, __shfl_xor_sync(0xffffffffu, m2, o));
        if (tid == 0) bc[0] = m2;
    }
    __syncthreads();
    const float m = bc[0];

    float s = 0.f;
#pragma unroll
    for (int i = 0; i < 16; i++) { f[i] = expf(f[i] - m); s += f[i]; }
#pragma unroll
    for (int o = 16; o; o >>= 1) s += __shfl_xor_sync(0xffffffffu, s, o);
    if ((tid & 31) == 0) red[tid >> 5] = s;
    __syncthreads();
    if (tid < 32) {
        float s2 = (tid < 8) ? red[tid] : 0.f;
#pragma unroll
        for (int o = 4; o; o >>= 1) s2 += __shfl_xor_sync(0xffffffffu, s2, o);
        if (tid == 0) bc[1] = s2;
    }
    __syncthreads();
    const float inv = 1.0f / bc[1];
#pragma unroll
    for (int j = 0; j < 2; j++) {
#pragma unroll
        for (int q = 0; q < 4; q++)
            v[j].h2[q] = __floats2half2_rn(f[j * 8 + q * 2] * inv, f[j * 8 + q * 2 + 1] * inv);
        ((uint4*)row)[tid + 256 * j] = v[j].u;
    }
}

// ---------------- context partials: ctx[d,e] = sum_n k[d,n] v[e,n] ---------
__global__ __launch_bounds__(256)
void k_ctx() {
    const int bh = blockIdx.x, sp = blockIdx.y;
    const int b = bh >> 3, h = bh & 7;
    const __half* kbase = g_kh + ((size_t)b * D_ + h * CH) * L_;
    const __half* vbase = g_vh + ((size_t)b * D_ + h * CH) * L_;

    __shared__ float ks[64][65];
    __shared__ float vs[64][65];
    const int tid = threadIdx.x;
    const int tx = tid & 15, ty = tid >> 4;

    float acc[4][4];
#pragma unroll
    for (int i = 0; i < 4; i++)
#pragma unroll
        for (int j = 0; j < 4; j++) acc[i][j] = 0.f;

    for (int chn = 0; chn < 8; chn++) {
        int n0 = sp * 512 + chn * 64;
#pragma unroll
        for (int i = 0; i < 4; i++) {
            int id = tid + 256 * i;               // 0..1023
            int arr = id >> 9;                    // 0 = k, 1 = v
            int idx = id & 511;
            int row = idx >> 3, u = idx & 7;      // 8 halves per unit
            const __half* src = (arr ? vbase : kbase) + (size_t)row * L_ + n0 + u * 8;
            union { uint4 q; __half2 h2[4]; } t;
            t.q = *(const uint4*)src;
            float* dstrow = (arr ? &vs[0][0] : &ks[0][0]) + row * 65 + u * 8;
#pragma unroll
            for (int qq = 0; qq < 4; qq++) {
                float2 p = __half22float2(t.h2[qq]);
                dstrow[qq * 2]     = p.x;
                dstrow[qq * 2 + 1] = p.y;
            }
        }
        __syncthreads();
#pragma unroll 4
        for (int nn = 0; nn < 64; nn++) {
            float kr[4], vr[4];
#pragma unroll
            for (int i = 0; i < 4; i++) kr[i] = ks[ty * 4 + i][nn];
#pragma unroll
            for (int j = 0; j < 4; j++) vr[j] = vs[tx + 16 * j][nn];
#pragma unroll
            for (int i = 0; i < 4; i++)
#pragma unroll
                for (int j = 0; j < 4; j++) acc[i][j] = fmaf(kr[i], vr[j], acc[i][j]);
        }
        __syncthreads();
    }
    float* out = g_ctxp + (size_t)(bh * 8 + sp) * 4096;
#pragma unroll
    for (int i = 0; i < 4; i++)
#pragma unroll
        for (int j = 0; j < 4; j++)
            out[(size_t)(ty * 4 + i) * 64 + tx + 16 * j] = acc[i][j];
}

// ---------------- reduce ctx + M = Wout-contract, emit fp16 ----------------
__global__ __launch_bounds__(256)
void k_M(const float* __restrict__ Wout) {
    const int bh = blockIdx.x;
    const int b = bh >> 3, h = bh & 7;
    __shared__ float ctxs[64][65];
    const int tid = threadIdx.x;

    for (int e0 = tid; e0 < 4096; e0 += 256) {
        float sum = 0.f;
        const float* p = g_ctxp + (size_t)bh * 8 * 4096 + e0;
#pragma unroll
        for (int s = 0; s < 8; s++) sum += p[(size_t)s * 4096];
        ctxs[e0 >> 6][e0 & 63] = sum;
    }
    __syncthreads();

    const int d = tid & 63, dq = tid >> 6;
    for (int dout = dq; dout < D_; dout += 4) {
        const float* wrow = Wout + (size_t)dout * D_ + h * CH;
        float sum = 0.f;
#pragma unroll
        for (int e = 0; e < CH; e++) sum = fmaf(__ldg(wrow + e), ctxs[d][e], sum);
        g_Mh[(size_t)b * D_ * D_ + (size_t)dout * D_ + h * CH + d] = __float2half(sum);
    }
}

// ---------------------------------------------------------------------------
extern "C" void kernel_launch(void* const* d_in, const int* in_sizes, int n_in,
                              void* d_out, int out_size) {
    const float* x    = (const float*)d_in[0];
    const float* Wqkv = (const float*)d_in[1];
    const float* Wout = (const float*)d_in[2];
    const float* bout = (const float*)d_in[3];
    float* y = (float*)d_out;

    cudaFuncSetAttribute(k_mm, cudaFuncAttributeMaxDynamicSharedMemorySize, SMEM_MM);

    int n4x = B_ * L_ * D_ / 4;
    int n4w = O3 * D_ / 4;
    k_split<<<(n4x + 255) / 256, 256>>>(x, 0, n4x);
    k_split<<<(n4w + 255) / 256, 256>>>(Wqkv, 1, n4w);

    k_mm<<<dim3(32, 12, B_), 256, SMEM_MM>>>(nullptr, nullptr, 0);    // qkv
    k_softmax_rows<<<dim3(512, B_), 256>>>();
    k_ctx<<<dim3(64, 8), 256>>>();
    k_M<<<64, 256>>>(Wout);
    k_mm<<<dim3(4, 32, B_), 256, SMEM_MM>>>(y, bout, 1);              // out
}

// round 13
// speedup vs baseline: 2.7222x; 1.0391x over previous
#include <cuda_runtime.h>
#include <cuda_fp16.h>
#include <cstdint>
#include <math.h>

#define B_  8
#define L_  4096
#define D_  512
#define H_  8
#define CH  64
#define O3  1536

// ---------------- scratch (__device__ globals; no allocs allowed) ----------
__device__ float g_ctxp[64 * 8 * 64 * 64];                     // [bh][split][d][e]
__device__ __half g_Wh[(size_t)O3 * D_];                       // W fp16
__device__ __half g_xh[(size_t)B_ * L_ * D_];                  // x fp16
__device__ __half g_qh[(size_t)B_ * L_ * D_];                  // q fp16 [b][l][c]
__device__ __half g_kh[(size_t)B_ * D_ * L_];                  // k fp16 [b][row][L]
__device__ __half g_vh[(size_t)B_ * D_ * L_];                  // v fp16 [b][row][L]
__device__ __half g_Mh[(size_t)B_ * D_ * D_];                  // M fp16

// ---------------- PTX helpers ---------------------------------------------
__device__ __forceinline__ uint32_t smem_u32(const void* p) {
    uint32_t a;
    asm("{ .reg .u64 t; cvta.to.shared.u64 t, %1; cvt.u32.u64 %0, t; }" : "=r"(a) : "l"(p));
    return a;
}
#define SWZ128(b) ((b) ^ (((b) >> 3) & 0x70))

__device__ __forceinline__ void cp16(uint32_t dst, const void* src) {
    asm volatile("cp.async.cg.shared.global [%0], [%1], 16;" :: "r"(dst), "l"(src));
}
#define CP_COMMIT() asm volatile("cp.async.commit_group;")

__device__ __forceinline__ void ldsm_x4(uint32_t r[4], uint32_t a) {
    asm volatile("ldmatrix.sync.aligned.m8n8.x4.shared.b16 {%0,%1,%2,%3}, [%4];"
                 : "=r"(r[0]), "=r"(r[1]), "=r"(r[2]), "=r"(r[3]) : "r"(a));
}
__device__ __forceinline__ void mma_f16(float d[4], const uint32_t a[4], const uint32_t b[2]) {
    asm volatile("mma.sync.aligned.m16n8k16.row.col.f32.f16.f16.f32 "
                 "{%0,%1,%2,%3}, {%4,%5,%6,%7}, {%8,%9}, {%0,%1,%2,%3};"
                 : "+f"(d[0]), "+f"(d[1]), "+f"(d[2]), "+f"(d[3])
                 : "r"(a[0]), "r"(a[1]), "r"(a[2]), "r"(a[3]), "r"(b[0]), "r"(b[1]));
}

// ---------------- Kernel: fp32 -> fp16 -------------------------------------
__global__ __launch_bounds__(256)
void k_split(const float* __restrict__ src, int which, int n4) {
    int i = blockIdx.x * 256 + threadIdx.x;
    if (i >= n4) return;
    float4 v = ((const float4*)src)[i];
    union { __half h[4]; uint2 u; } ph;
    ph.h[0] = __float2half(v.x); ph.h[1] = __float2half(v.y);
    ph.h[2] = __float2half(v.z); ph.h[3] = __float2half(v.w);
    __half* dst = which ? g_Wh : g_xh;
    *(uint2*)(dst + (size_t)i * 4) = ph.u;
}

// ---------------- mma.sync fp16 single-pass GEMM, 3-stage ------------------
// D[m,n] = sum_k A[m,k]*B[n,k]; both fp16, fp32 accum.
// CTA 128x128, 8 warps (2m x 4n), K-chunk 64, 3-stage cp.async,
// ONE barrier per chunk; B fragments via x4 (two nt-tiles per ldmatrix).
// mode 0: qkv (A=W, B=x; m0<512 -> fused q-softmax -> g_qh; else fp16 k/v)
// mode 1: out (A=q, B=M; D+bias -> y fp32)
#define STAGE_B  32768
#define SMEM_MM  (3 * STAGE_B)

__global__ __launch_bounds__(256, 2)
void k_mm(float* __restrict__ Cout, const float* __restrict__ bias, int mode) {
    extern __shared__ char smem[];
    const int tid  = threadIdx.x;
    const int wid  = tid >> 5, lane = tid & 31;
    const int wm   = wid & 1;          // m offset wm*64
    const int wn   = wid >> 1;         // n offset wn*32
    const int b    = blockIdx.z;
    const int m0   = blockIdx.y * 128;
    const int n0   = blockIdx.x * 128;

    const uint32_t smbase = smem_u32(smem);

    const __half *Ah, *Bh;
    if (mode == 0) {
        Ah = g_Wh + (size_t)m0 * D_;
        Bh = g_xh + ((size_t)b * L_ + n0) * D_;
    } else {
        Ah = g_qh + ((size_t)b * L_ + m0) * D_;
        Bh = g_Mh + ((size_t)b * D_ + n0) * D_;
    }

    auto load_stage = [&](int s, int d0) {
        uint32_t base = smbase + s * STAGE_B;
#pragma unroll
        for (int i = 0; i < 8; i++) {
            int id = i * 256 + tid;                // 0..2047
            int pl = id >> 10;                     // 0=A, 1=B
            int r  = (id >> 3) & 127;
            int u  = id & 7;
            const __half* src = (pl ? Bh : Ah) + (size_t)r * D_ + d0 + u * 8;
            cp16(base + pl * 16384 + SWZ128((uint32_t)(r * 128 + u * 16)), src);
        }
        CP_COMMIT();
    };

    float acc[4][4][4];
#pragma unroll
    for (int i = 0; i < 4; i++)
#pragma unroll
        for (int j = 0; j < 4; j++)
#pragma unroll
            for (int k = 0; k < 4; k++) acc[i][j][k] = 0.f;

    // A lanes: rows 16/matrix-pair, units by lane>>4
    const uint32_t a_row = wm * 64 + (lane & 15);
    const uint32_t a_ub  = (lane >> 4);
    // B lanes (x4, two nt tiles): g0/g1 -> rows nt2j, k-lo/hi; g2/g3 -> nt2j+1
    const uint32_t b_row = wn * 32 + (lane & 7) + ((lane >> 4) << 3);
    const uint32_t b_ub  = (lane >> 3) & 1;

    load_stage(0, 0);
    load_stage(1, 64);

#pragma unroll
    for (int kc = 0; kc < 8; kc++) {
        const int s = kc % 3;
        if (kc < 7) asm volatile("cp.async.wait_group 1;");
        else        asm volatile("cp.async.wait_group 0;");
        __syncthreads();
        if (kc + 2 < 8) load_stage((kc + 2) % 3, (kc + 2) * 64);

        uint32_t smA = smbase + s * STAGE_B;
        uint32_t smB = smA + 16384;
#pragma unroll
        for (int sl = 0; sl < 4; sl++) {
            uint32_t bb[2][4];                     // [pair j][4 regs]
#pragma unroll
            for (int j = 0; j < 2; j++)
                ldsm_x4(bb[j], smB + SWZ128((b_row + j * 16) * 128 + (sl * 2 + b_ub) * 16));
            uint32_t ah[4][4];
#pragma unroll
            for (int mt = 0; mt < 4; mt++)
                ldsm_x4(ah[mt], smA + SWZ128((a_row + mt * 16) * 128 + (sl * 2 + a_ub) * 16));
#pragma unroll
            for (int j = 0; j < 2; j++)
#pragma unroll
                for (int half = 0; half < 2; half++) {
                    const uint32_t* bf = &bb[j][half * 2];   // nt = 2j+half
#pragma unroll
                    for (int mt = 0; mt < 4; mt++)
                        mma_f16(acc[mt][j * 2 + half], ah[mt], bf);
                }
        }
    }
    __syncthreads();

    // ---- epilogue via smem, two 64-col halves ----
    float* ep = (float*)smem;                      // [128][65]
    float* inv_s = ep + 128 * 65;                  // [2][64]
    for (int p = 0; p < 2; p++) {
        if ((wn >> 1) == p) {
            int cb = (wn & 1) * 32;
#pragma unroll
            for (int mt = 0; mt < 4; mt++)
#pragma unroll
                for (int nt = 0; nt < 4; nt++) {
                    int row = wm * 64 + mt * 16 + (lane >> 2);
                    int col = cb + nt * 8 + (lane & 3) * 2;
                    ep[row * 65 + col]           = acc[mt][nt][0];
                    ep[row * 65 + col + 1]       = acc[mt][nt][1];
                    ep[(row + 8) * 65 + col]     = acc[mt][nt][2];
                    ep[(row + 8) * 65 + col + 1] = acc[mt][nt][3];
                }
        }
        __syncthreads();
        int c0 = p * 64;
        if (mode == 0 && m0 < 512) {
            // fused q-softmax over channel dim (64 rows/head, 2 heads/tile)
            if (tid < 128) {
                int c  = tid & 63;
                int r0 = (tid >> 6) * 64;
                float mx = -3.0e38f;
#pragma unroll 8
                for (int r = 0; r < 64; r++) mx = fmaxf(mx, ep[(r0 + r) * 65 + c]);
                float s = 0.f;
#pragma unroll 8
                for (int r = 0; r < 64; r++) {
                    float e = expf(ep[(r0 + r) * 65 + c] - mx);
                    ep[(r0 + r) * 65 + c] = e;
                    s += e;
                }
                inv_s[tid] = 1.0f / s;
            }
            __syncthreads();
#pragma unroll
            for (int i = 0; i < 8; i++) {
                int id = tid + 256 * i;
                int c = id >> 5, mg = id & 31;
                float inv = inv_s[(mg >> 4) * 64 + c];
                union { __half h[4]; uint2 u; } ph;
                ph.h[0] = __float2half(ep[(mg * 4 + 0) * 65 + c] * inv);
                ph.h[1] = __float2half(ep[(mg * 4 + 1) * 65 + c] * inv);
                ph.h[2] = __float2half(ep[(mg * 4 + 2) * 65 + c] * inv);
                ph.h[3] = __float2half(ep[(mg * 4 + 3) * 65 + c] * inv);
                *(uint2*)(g_qh + ((size_t)b * L_ + n0 + c0 + c) * D_ + m0 + mg * 4) = ph.u;
            }
        } else if (mode == 0) {
            // k / v -> fp16 [b][row][L]
            __half* dst = (m0 < 1024)
                ? g_kh + ((size_t)b * D_ + (m0 - 512))  * L_
                : g_vh + ((size_t)b * D_ + (m0 - 1024)) * L_;
#pragma unroll
            for (int i = 0; i < 8; i++) {
                int id = tid + 256 * i;
                int m = id >> 4, g = id & 15;
                union { __half h[4]; uint2 u; } ph;
                ph.h[0] = __float2half(ep[m * 65 + g * 4 + 0]);
                ph.h[1] = __float2half(ep[m * 65 + g * 4 + 1]);
                ph.h[2] = __float2half(ep[m * 65 + g * 4 + 2]);
                ph.h[3] = __float2half(ep[m * 65 + g * 4 + 3]);
                *(uint2*)(dst + (size_t)m * L_ + n0 + c0 + g * 4) = ph.u;
            }
        } else {
            float* dst = Cout + ((size_t)b * L_ + m0) * D_;
#pragma unroll
            for (int i = 0; i < 8; i++) {
                int id = tid + 256 * i;
                int m = id >> 4, g = id & 15;
                float4 v;
                v.x = ep[m * 65 + g * 4 + 0] + __ldg(bias + n0 + c0 + g * 4 + 0);
                v.y = ep[m * 65 + g * 4 + 1] + __ldg(bias + n0 + c0 + g * 4 + 1);
                v.z = ep[m * 65 + g * 4 + 2] + __ldg(bias + n0 + c0 + g * 4 + 2);
                v.w = ep[m * 65 + g * 4 + 3] + __ldg(bias + n0 + c0 + g * 4 + 3);
                *(float4*)(dst + (size_t)m * D_ + n0 + c0 + g * 4) = v;
            }
        }
        __syncthreads();
    }
}

// ---------------- softmax over L for k rows (fp16 storage) -----------------
__global__ __launch_bounds__(256)
void k_softmax_rows() {
    const int r = blockIdx.x, b = blockIdx.y;
    __half* row = g_kh + ((size_t)b * D_ + r) * L_;
    const int tid = threadIdx.x;
    __shared__ float red[8], bc[2];

    union { uint4 u; __half2 h2[4]; } v[2];
    float f[16];
    float mx = -3.0e38f;
#pragma unroll
    for (int j = 0; j < 2; j++) {
        v[j].u = ((const uint4*)row)[tid + 256 * j];
#pragma unroll
        for (int q = 0; q < 4; q++) {
            float2 p = __half22float2(v[j].h2[q]);
            f[j * 8 + q * 2]     = p.x;
            f[j * 8 + q * 2 + 1] = p.y;
            mx = fmaxf(mx, fmaxf(p.x, p.y));
        }
    }
#pragma unroll
    for (int o = 16; o; o >>= 1) mx = fmaxf(mx, __shfl_xor_sync(0xffffffffu, mx, o));
    if ((tid & 31) == 0) red[tid >> 5] = mx;
    __syncthreads();
    if (tid < 32) {
        float m2 = (tid < 8) ? red[tid] : -3.0e38f;
#pragma unroll
        for (int o = 4; o; o >>= 1) m2 = fmaxf(m2, __shfl_xor_sync(0xffffffffu, m2, o));
        if (tid == 0) bc[0] = m2;
    }
    __syncthreads();
    const float m = bc[0];

    float s = 0.f;
#pragma unroll
    for (int i = 0; i < 16; i++) { f[i] = expf(f[i] - m); s += f[i]; }
#pragma unroll
    for (int o = 16; o; o >>= 1) s += __shfl_xor_sync(0xffffffffu, s, o);
    if ((tid & 31) == 0) red[tid >> 5] = s;
    __syncthreads();
    if (tid < 32) {
        float s2 = (tid < 8) ? red[tid] : 0.f;
#pragma unroll
        for (int o = 4; o; o >>= 1) s2 += __shfl_xor_sync(0xffffffffu, s2, o);
        if (tid == 0) bc[1] = s2;
    }
    __syncthreads();
    const float inv = 1.0f / bc[1];
#pragma unroll
    for (int j = 0; j < 2; j++) {
#pragma unroll
        for (int q = 0; q < 4; q++)
            v[j].h2[q] = __floats2half2_rn(f[j * 8 + q * 2] * inv, f[j * 8 + q * 2 + 1] * inv);
        ((uint4*)row)[tid + 256 * j] = v[j].u;
    }
}

// ---------------- context partials: ctx[d,e] = sum_n k[d,n] v[e,n] ---------
__global__ __launch_bounds__(256)
void k_ctx() {
    const int bh = blockIdx.x, sp = blockIdx.y;
    const int b = bh >> 3, h = bh & 7;
    const __half* kbase = g_kh + ((size_t)b * D_ + h * CH) * L_;
    const __half* vbase = g_vh + ((size_t)b * D_ + h * CH) * L_;

    __shared__ float ks[64][65];
    __shared__ float vs[64][65];
    const int tid = threadIdx.x;
    const int tx = tid & 15, ty = tid >> 4;

    float acc[4][4];
#pragma unroll
    for (int i = 0; i < 4; i++)
#pragma unroll
        for (int j = 0; j < 4; j++) acc[i][j] = 0.f;

    for (int chn = 0; chn < 8; chn++) {
        int n0 = sp * 512 + chn * 64;
#pragma unroll
        for (int i = 0; i < 4; i++) {
            int id = tid + 256 * i;               // 0..1023
            int arr = id >> 9;                    // 0 = k, 1 = v
            int idx = id & 511;
            int row = idx >> 3, u = idx & 7;
            const __half* src = (arr ? vbase : kbase) + (size_t)row * L_ + n0 + u * 8;
            union { uint4 q; __half2 h2[4]; } t;
            t.q = *(const uint4*)src;
            float* dstrow = (arr ? &vs[0][0] : &ks[0][0]) + row * 65 + u * 8;
#pragma unroll
            for (int qq = 0; qq < 4; qq++) {
                float2 p = __half22float2(t.h2[qq]);
                dstrow[qq * 2]     = p.x;
                dstrow[qq * 2 + 1] = p.y;
            }
        }
        __syncthreads();
#pragma unroll 4
        for (int nn = 0; nn < 64; nn++) {
            float kr[4], vr[4];
#pragma unroll
            for (int i = 0; i < 4; i++) kr[i] = ks[ty * 4 + i][nn];
#pragma unroll
            for (int j = 0; j < 4; j++) vr[j] = vs[tx + 16 * j][nn];
#pragma unroll
            for (int i = 0; i < 4; i++)
#pragma unroll
                for (int j = 0; j < 4; j++) acc[i][j] = fmaf(kr[i], vr[j], acc[i][j]);
        }
        __syncthreads();
    }
    float* out = g_ctxp + (size_t)(bh * 8 + sp) * 4096;
#pragma unroll
    for (int i = 0; i < 4; i++)
#pragma unroll
        for (int j = 0; j < 4; j++)
            out[(size_t)(ty * 4 + i) * 64 + tx + 16 * j] = acc[i][j];
}

// ---------------- reduce ctx + M = Wout-contract, emit fp16 ----------------
__global__ __launch_bounds__(256)
void k_M(const float* __restrict__ Wout) {
    const int bh = blockIdx.x;
    const int b = bh >> 3, h = bh & 7;
    __shared__ float ctxs[64][65];
    const int tid = threadIdx.x;

    for (int e0 = tid; e0 < 4096; e0 += 256) {
        float sum = 0.f;
        const float* p = g_ctxp + (size_t)bh * 8 * 4096 + e0;
#pragma unroll
        for (int s = 0; s < 8; s++) sum += p[(size_t)s * 4096];
        ctxs[e0 >> 6][e0 & 63] = sum;
    }
    __syncthreads();

    const int d = tid & 63, dq = tid >> 6;
    for (int dout = dq; dout < D_; dout += 4) {
        const float* wrow = Wout + (size_t)dout * D_ + h * CH;
        float sum = 0.f;
#pragma unroll
        for (int e = 0; e < CH; e++) sum = fmaf(__ldg(wrow + e), ctxs[d][e], sum);
        g_Mh[(size_t)b * D_ * D_ + (size_t)dout * D_ + h * CH + d] = __float2half(sum);
    }
}

// ---------------------------------------------------------------------------
extern "C" void kernel_launch(void* const* d_in, const int* in_sizes, int n_in,
                              void* d_out, int out_size) {
    const float* x    = (const float*)d_in[0];
    const float* Wqkv = (const float*)d_in[1];
    const float* Wout = (const float*)d_in[2];
    const float* bout = (const float*)d_in[3];
    float* y = (float*)d_out;

    cudaFuncSetAttribute(k_mm, cudaFuncAttributeMaxDynamicSharedMemorySize, SMEM_MM);

    int n4x = B_ * L_ * D_ / 4;
    int n4w = O3 * D_ / 4;
    k_split<<<(n4x + 255) / 256, 256>>>(x, 0, n4x);
    k_split<<<(n4w + 255) / 256, 256>>>(Wqkv, 1, n4w);

    k_mm<<<dim3(32, 12, B_), 256, SMEM_MM>>>(nullptr, nullptr, 0);    // qkv
    k_softmax_rows<<<dim3(512, B_), 256>>>();
    k_ctx<<<dim3(64, 8), 256>>>();
    k_M<<<64, 256>>>(Wout);
    k_mm<<<dim3(4, 32, B_), 256, SMEM_MM>>>(y, bout, 1);              // out
}